// round 17
// baseline (speedup 1.0000x reference)
#include <cuda_runtime.h>
#include <math.h>

#define BB 2
#define NN 262144
#define KK 9      // K+1 slots
#define DD 64
#define SS 64
#define PTS 128   // points per tile
#define NTILES ((BB * NN) / PTS)   // 4096
#define BG_BOUND 1.0f
#define SCALE_F 0.125f

// ---------------------------------------------------------------------------
// Folded per-batch operands; computed on device, copied into __constant__.
// ---------------------------------------------------------------------------
struct __align__(16) PreData {
    float M[BB][KK][DD];   // M = K @ Wq          (logit matrix)
    float P[BB][KK][DD];   // P = slots_full @ out_w^T
    float c[BB][KK];       // c = K @ Wq_b
    float ob[DD];          // out_b
    float ds;              // exp(density_scale)
};
__device__    PreData g_pre;
__constant__  PreData c_pre;
__device__ unsigned int g_ctr;         // work-stealing tile counter

// ---------------------------------------------------------------------------
// Precompute: one block per (batch, slot) pair -> 18 blocks, 64 threads.
// Also resets the work counter (precompute precedes main in the graph).
// ---------------------------------------------------------------------------
__global__ __launch_bounds__(64)
void precompute(const float* __restrict__ slots,
                const float* __restrict__ empty_slot,
                const float* __restrict__ Wq_w,
                const float* __restrict__ Wq_b,
                const float* __restrict__ Wk_w,
                const float* __restrict__ Wk_b,
                const float* __restrict__ out_w,
                const float* __restrict__ out_b,
                const float* __restrict__ dscale)
{
    __shared__ float sSlot[SS];
    __shared__ float sK[DD];

    const int b = blockIdx.x / KK;
    const int j = blockIdx.x % KK;
    const int d = threadIdx.x;

    if (blockIdx.x == 0 && d == 0) g_ctr = 0;   // deterministic counter reset

    sSlot[d] = (j == 0) ? empty_slot[d]
                        : slots[((size_t)b * (KK - 1) + (j - 1)) * SS + d];
    __syncthreads();

    const float4* wk4 = reinterpret_cast<const float4*>(Wk_w  + d * SS);
    const float4* ow4 = reinterpret_cast<const float4*>(out_w + d * SS);
    float kk = Wk_b[d];
    float pp = 0.f;
#pragma unroll
    for (int i = 0; i < SS / 4; i++) {
        const float4 wv = wk4[i];
        const float4 ov = ow4[i];
        const float s0 = sSlot[4 * i], s1 = sSlot[4 * i + 1];
        const float s2 = sSlot[4 * i + 2], s3 = sSlot[4 * i + 3];
        kk = fmaf(s0, wv.x, fmaf(s1, wv.y, fmaf(s2, wv.z, fmaf(s3, wv.w, kk))));
        pp = fmaf(s0, ov.x, fmaf(s1, ov.y, fmaf(s2, ov.z, fmaf(s3, ov.w, pp))));
    }
    sK[d] = kk;
    g_pre.P[b][j][d] = pp;

    if (blockIdx.x == 0) {
        g_pre.ob[d] = out_b[d];
        if (d == 0) g_pre.ds = __expf(dscale[0]);
    }
    __syncthreads();

    float m = 0.f;
#pragma unroll 8
    for (int dd = 0; dd < DD; dd++)
        m = fmaf(sK[dd], Wq_w[dd * DD + d], m);
    g_pre.M[b][j][d] = m;

    if (d == 0) {
        float cc = 0.f;
        for (int dd = 0; dd < DD; dd++)
            cc = fmaf(Wq_b[dd], sK[dd], cc);
        g_pre.c[b][j] = cc;
    }
}

// ---------------------------------------------------------------------------
// Main kernel: persistent 128-thread blocks pulling 128-point tiles from a
// global counter. Removes wave quantization (4096 tiles / ~3.46 waves) and
// load-balances the cross-CTA spread. Tile body identical to R16.
// ---------------------------------------------------------------------------
__global__ __launch_bounds__(128)
void joint_decoder_main(const float* __restrict__ pf,
                        const float* __restrict__ coor,
                        float* __restrict__ xo,
                        float* __restrict__ wout,
                        float* __restrict__ sig)
{
    __shared__ float4 sT4[4][130];       // conflict-free transpose tile
    __shared__ float  sW[PTS * KK];      // staged w for coalesced stores
    __shared__ unsigned int sTile;

    const int tid = threadIdx.x;

    for (;;) {
        if (tid == 0) sTile = atomicAdd(&g_ctr, 1u);
        __syncthreads();                 // broadcast tile id; also orders
        const unsigned int t = sTile;    // prev tile's sW reads vs new writes
        if (t >= NTILES) break;

        const int p0 = t * PTS;
        const int b  = (int)(t >> 11);   // 2048 tiles per batch
        const int p  = p0 + tid;

        const float4* pf4 = reinterpret_cast<const float4*>(pf + (size_t)p0 * DD);

        // ---- Phase 1: logits via 4 transposed input tiles ----
        float l[KK];                     // acc -> logit -> e -> w (in place)
#pragma unroll
        for (int j = 0; j < KK; j++) l[j] = 0.f;

#pragma unroll
        for (int it = 0; it < 4; it++) {
            if (it) __syncthreads();             // previous tile consumed
#pragma unroll
            for (int r = 0; r < 4; r++) {
                const int q = r * 128 + tid;
                sT4[q & 3][q >> 2] = pf4[(q >> 2) * 16 + it * 4 + (q & 3)];
            }
            __syncthreads();
#pragma unroll
            for (int ii = 0; ii < 4; ii++) {
                const float4 x = sT4[ii][tid];
                const int i4 = (it * 4 + ii) * 4;
#pragma unroll
                for (int j = 0; j < KK; j++) {
                    const float4 m = *reinterpret_cast<const float4*>(
                                         &c_pre.M[b][j][i4]);    // LDCU.128
                    l[j] = fmaf(x.x, m.x,
                           fmaf(x.y, m.y,
                           fmaf(x.z, m.z,
                           fmaf(x.w, m.w, l[j]))));
                }
            }
        }
        __syncthreads();                         // sT4 free for output phase

#pragma unroll
        for (int j = 0; j < KK; j++)
            l[j] = (l[j] + c_pre.c[b][j]) * SCALE_F;

        // ---- force_bg mask: direct scalar LDG ----
        const float* cp = coor + (size_t)p * 3;
        const float c0 = cp[0], c1 = cp[1], c2 = cp[2];
        const bool inb = (fabsf(c0) <= BG_BOUND) && (fabsf(c1) <= BG_BOUND) &&
                         (fabsf(c2) <= BG_BOUND);

        // ---- masked softmax + density, single array in place ----
        float mx = fmaxf(l[0], l[1]);
        if (inb) {
#pragma unroll
            for (int j = 2; j < KK; j++) mx = fmaxf(mx, l[j]);
        }
        float s, sg = 0.f;
        {
            const float e0 = __expf(l[0] - mx);
            l[0] = e0; s = e0;
        }
#pragma unroll
        for (int j = 1; j < KK; j++) {
            const float e = (j < 2 || inb) ? __expf(l[j] - mx) : 0.f;
            sg = fmaf(fmaxf(l[j], 0.f), e, sg);  // pre-normalization density
            l[j] = e; s += e;
        }
        const float inv = __frcp_rn(s);
#pragma unroll
        for (int j = 0; j < KK; j++) l[j] *= inv;    // l[] now holds w[]
        sig[p] = sg * inv * c_pre.ds;

#pragma unroll
        for (int j = 0; j < KK; j++) sW[tid * KK + j] = l[j];  // stride 9: no conflicts

        // ---- Phase 2: xo via 4 transposed output tiles ----
        float4* xo4 = reinterpret_cast<float4*>(xo + (size_t)p0 * DD);
#pragma unroll
        for (int it = 0; it < 4; it++) {
            if (it) __syncthreads();             // previous tile drained
#pragma unroll
            for (int ii = 0; ii < 4; ii++) {
                const int i4 = (it * 4 + ii) * 4;
                float4 o = *reinterpret_cast<const float4*>(&c_pre.ob[i4]);
#pragma unroll
                for (int j = 0; j < KK; j++) {
                    const float4 q = *reinterpret_cast<const float4*>(
                                         &c_pre.P[b][j][i4]);    // LDCU.128
                    o.x = fmaf(l[j], q.x, o.x);
                    o.y = fmaf(l[j], q.y, o.y);
                    o.z = fmaf(l[j], q.z, o.z);
                    o.w = fmaf(l[j], q.w, o.w);
                }
                sT4[ii][tid] = o;
            }
            __syncthreads();
#pragma unroll
            for (int r = 0; r < 4; r++) {
                const int q = r * 128 + tid;
                xo4[(q >> 2) * 16 + it * 4 + (q & 3)] = sT4[q & 3][q >> 2];
            }
        }

        // ---- w out: float4-coalesced copy (ordered by phase-2 barriers) ----
        {
            const float4* sw4 = reinterpret_cast<const float4*>(sW);
            float4* wg4 = reinterpret_cast<float4*>(wout + (size_t)p0 * KK);
            wg4[tid]       = sw4[tid];
            wg4[tid + 128] = sw4[tid + 128];
            if (tid < 32) wg4[tid + 256] = sw4[tid + 256];
        }
        // next-tile broadcast barrier orders these sW reads vs future writes
    }
}

// ---------------------------------------------------------------------------
// Launch
// ---------------------------------------------------------------------------
extern "C" void kernel_launch(void* const* d_in, const int* in_sizes, int n_in,
                              void* d_out, int out_size)
{
    const float* pf     = (const float*)d_in[0];   // point_feats [B,N,D]
    const float* slots  = (const float*)d_in[2];   // [B,K,S]
    const float* coor   = (const float*)d_in[3];   // [B,N,3]
    const float* empty  = (const float*)d_in[4];   // [1,1,S]
    const float* Wq_w   = (const float*)d_in[5];
    const float* Wq_b   = (const float*)d_in[6];
    const float* Wk_w   = (const float*)d_in[7];
    const float* Wk_b   = (const float*)d_in[8];
    const float* out_w  = (const float*)d_in[9];
    const float* out_b  = (const float*)d_in[10];
    const float* dscale = (const float*)d_in[11];

    float* out  = (float*)d_out;
    float* xo   = out;                              // [B,N,64]
    float* wout = out + (size_t)BB * NN * DD;       // [B,N,9]
    float* sig  = wout + (size_t)BB * NN * KK;      // [B,N]

    precompute<<<BB * KK, 64>>>(slots, empty, Wq_w, Wq_b, Wk_w, Wk_b,
                                out_w, out_b, dscale);

    void* g_pre_addr = nullptr;
    cudaGetSymbolAddress(&g_pre_addr, g_pre);
    cudaMemcpyToSymbolAsync(c_pre, g_pre_addr, sizeof(PreData), 0,
                            cudaMemcpyDeviceToDevice);

    // Persistent grid: 8 blocks per SM on 148 SMs; work-stealing covers all
    // tiles regardless of actual residency.
    joint_decoder_main<<<148 * 8, 128>>>(pf, coor, xo, wout, sig);
}